// round 1
// baseline (speedup 1.0000x reference)
#include <cuda_runtime.h>
#include <math.h>

#define NE 50000
#define NN 25000
#define NG 1024
#define HID 128

// ---------------- scratch (device globals; no runtime allocation) ----------
__device__ float g_h[NE * HID];      // edge MLP hidden, recomputed per layer
__device__ float g_xa[NN * 64];      // node feature ping
__device__ float g_xb[NN * 64];      // node feature pong
__device__ float g_acc[NN * 64];     // accumulation buffer (root + scatter)
__device__ float g_sums[NG * 64];
__device__ float g_cnt[NG];
__device__ int   g_src[NE];
__device__ int   g_dst[NE];
__device__ int   g_batch[NN];
__device__ int   g_is64;

__device__ __forceinline__ float eluf(float v) { return v > 0.f ? v : expm1f(v); }

// ---------------- index dtype detection + conversion ----------------------
// Reference asks for int64, but JAX w/o x64 silently produces int32. Detect:
// if buffer is int32 pairs, reinterpreting as int64 gives values >= 2^32
// almost surely within the first 256 entries (values are < 25000).
__global__ void detect_kernel(const long long* __restrict__ ei) {
    if (blockIdx.x == 0 && threadIdx.x == 0) {
        int is64 = 1;
        for (int i = 0; i < 256; i++) {            // 2KB read, safe either way
            long long v = ei[i];
            if (v < 0 || v >= (long long)NN) { is64 = 0; break; }
        }
        g_is64 = is64;
    }
}

__global__ void convert_kernel(const void* __restrict__ ei, const void* __restrict__ bat) {
    int t = blockIdx.x * blockDim.x + threadIdx.x;
    const int is64 = g_is64;
    if (t < NE) {
        if (is64) {
            g_src[t] = (int)((const long long*)ei)[t];
            g_dst[t] = (int)((const long long*)ei)[NE + t];
        } else {
            g_src[t] = ((const int*)ei)[t];
            g_dst[t] = ((const int*)ei)[NE + t];
        }
    }
    if (t < NN) {
        g_batch[t] = is64 ? (int)((const long long*)bat)[t] : ((const int*)bat)[t];
    }
}

// ---------------- edge MLP: h = relu(edge_attr @ w1 + b1) ------------------
__global__ void edge_h_kernel(const float* __restrict__ ea,
                              const float* __restrict__ w1,
                              const float* __restrict__ b1) {
    int t = blockIdx.x * blockDim.x + threadIdx.x;
    if (t >= NE * HID) return;
    int e = t >> 7, k = t & 127;
    const float* a = ea + e * 5;
    float s = b1[k];
#pragma unroll
    for (int d = 0; d < 5; d++) s = fmaf(a[d], w1[d * HID + k], s);
    g_h[t] = fmaxf(s, 0.f);
}

// ---------------- acc = x @ root + bias (also zero-inits the scatter target)
template<int M_IN, int M_OUT>
__global__ void root_kernel(const float* __restrict__ x,
                            const float* __restrict__ root,
                            const float* __restrict__ bias,
                            float* __restrict__ acc) {
    int t = blockIdx.x * blockDim.x + threadIdx.x;
    if (t >= NN * M_OUT) return;
    int n = t / M_OUT, o = t - n * M_OUT;
    const float* xr = x + n * M_IN;
    float s = bias[o];
#pragma unroll
    for (int i = 0; i < M_IN; i++) s = fmaf(xr[i], root[i * M_OUT + o], s);
    acc[t] = s;
}

__global__ void elu_kernel(const float* __restrict__ acc, float* __restrict__ xo, int n) {
    int t = blockIdx.x * blockDim.x + threadIdx.x;
    if (t < n) xo[t] = eluf(acc[t]);
}

// ---------------- fused per-edge message GEMM + scatter --------------------
// msg[e,o] = sum_{k,i} h[e,k]*x[src,i]*w2[k,i,o] + sum_i x[src,i]*b2[i,o]
// Block: TM edges x M_OUT outputs. Per k-step: build u[i][e]=h[e,k]*x[e,i]
// in smem (transposed, conflict-free), then 4x4 register-tiled FMA stream
// fed by LDS.128(u) + LDG.128(w2, L1/L2 resident). Epilogue: atomicAdd.
template<int M_IN, int M_OUT, int TM>
__global__ void __launch_bounds__(128)
msg_kernel(const float* __restrict__ xin,
           const float* __restrict__ w2,
           const float* __restrict__ b2,
           float* __restrict__ acc) {
    constexpr int RE = 4, QO = 4;
    constexpr int TX = M_OUT / QO;                 // 8 (L1) or 16 (L2/L3)
    __shared__ __align__(16) float h_T[HID * (TM + 1)];  // [k][e], padded
    __shared__ __align__(16) float x_T[M_IN * TM];       // [i][e]
    __shared__ __align__(16) float u_s[M_IN * TM];       // [i][e]
    __shared__ int src_s[TM];
    __shared__ int dst_s[TM];

    const int tid  = threadIdx.x;
    const int e0   = blockIdx.x * TM;
    const int ecnt = min(TM, NE - e0);

    if (tid < TM) {
        src_s[tid] = (tid < ecnt) ? g_src[e0 + tid] : 0;
        dst_s[tid] = (tid < ecnt) ? g_dst[e0 + tid] : -1;
    }
    __syncthreads();
    for (int t = tid; t < M_IN * TM; t += 128) {
        int i = t / TM;
        int e = t - i * TM;
        x_T[t] = (e < ecnt) ? xin[src_s[e] * M_IN + i] : 0.f;
    }
    for (int t = tid; t < HID * TM; t += 128) {
        int e = t >> 7;                 // coalesced global read (HID==128)
        int k = t & (HID - 1);
        h_T[k * (TM + 1) + e] = (e < ecnt) ? g_h[(e0 + e) * HID + k] : 0.f;
    }

    const int tx = tid % TX;
    const int ty = tid / TX;
    const int ob = tx * QO;
    const int eb = ty * RE;

    float a[RE][QO];
#pragma unroll
    for (int r = 0; r < RE; r++)
#pragma unroll
        for (int q = 0; q < QO; q++) a[r][q] = 0.f;

    for (int k = 0; k < HID; k++) {
        __syncthreads();                // protect u_s from prior-k readers
        for (int t = tid; t < M_IN * TM; t += 128)
            u_s[t] = h_T[k * (TM + 1) + (t & (TM - 1))] * x_T[t];
        __syncthreads();
        const float* w2k = w2 + k * (M_IN * M_OUT);
#pragma unroll 16
        for (int i = 0; i < M_IN; i++) {
            float4 w = *(const float4*)(w2k + i * M_OUT + ob);
            float4 u = *(const float4*)(u_s + i * TM + eb);
            float ur[4] = {u.x, u.y, u.z, u.w};
            float wq[4] = {w.x, w.y, w.z, w.w};
#pragma unroll
            for (int r = 0; r < RE; r++)
#pragma unroll
                for (int q = 0; q < QO; q++)
                    a[r][q] = fmaf(ur[r], wq[q], a[r][q]);
        }
    }
    // b2 term: sum_i x[e,i]*b2[i,o]
#pragma unroll 16
    for (int i = 0; i < M_IN; i++) {
        float4 bb = *(const float4*)(b2 + i * M_OUT + ob);
        float4 xx = *(const float4*)(x_T + i * TM + eb);
        float xr[4] = {xx.x, xx.y, xx.z, xx.w};
        float bq[4] = {bb.x, bb.y, bb.z, bb.w};
#pragma unroll
        for (int r = 0; r < RE; r++)
#pragma unroll
            for (int q = 0; q < QO; q++)
                a[r][q] = fmaf(xr[r], bq[q], a[r][q]);
    }
    // scatter-add epilogue
#pragma unroll
    for (int r = 0; r < RE; r++) {
        int d = dst_s[eb + r];
        if (d >= 0) {
            float* p = acc + d * M_OUT + ob;
#pragma unroll
            for (int q = 0; q < QO; q++) atomicAdd(p + q, a[r][q]);
        }
    }
}

// ---------------- pooling + final MLP --------------------------------------
__global__ void pool_init_kernel() {
    int t = blockIdx.x * blockDim.x + threadIdx.x;
    if (t < NG * 64) g_sums[t] = 0.f;
    if (t < NG) g_cnt[t] = 0.f;
}

__global__ void pool_kernel(const float* __restrict__ x) {
    int t = blockIdx.x * blockDim.x + threadIdx.x;
    if (t >= NN * 64) return;
    int n = t >> 6, o = t & 63;
    int g = g_batch[n];
    atomicAdd(&g_sums[g * 64 + o], x[t]);
    if (o == 0) atomicAdd(&g_cnt[g], 1.f);
}

__global__ void __launch_bounds__(128)
mlp_kernel(const float* __restrict__ fc1_w, const float* __restrict__ fc1_b,
           const float* __restrict__ fc2_w, const float* __restrict__ fc2_b,
           const float* __restrict__ fc3_w, const float* __restrict__ fc3_b,
           float* __restrict__ out) {
    int g = blockIdx.x * blockDim.x + threadIdx.x;
    if (g >= NG) return;
    float inv = 1.f / fmaxf(g_cnt[g], 1.f);
    const float* srow = g_sums + g * 64;
    float h1[32];
#pragma unroll
    for (int j = 0; j < 32; j++) {
        float s = 0.f;
#pragma unroll
        for (int i = 0; i < 64; i++) s = fmaf(srow[i], fc1_w[i * 32 + j], s);
        h1[j] = eluf(fmaf(s, inv, fc1_b[j]));
    }
    float h2[16];
#pragma unroll
    for (int j = 0; j < 16; j++) {
        float s = fc2_b[j];
#pragma unroll
        for (int i = 0; i < 32; i++) s = fmaf(h1[i], fc2_w[i * 16 + j], s);
        h2[j] = eluf(s);
    }
    float s = fc3_b[0];
#pragma unroll
    for (int i = 0; i < 16; i++) s = fmaf(h2[i], fc3_w[i], s);
    out[g] = s;
}

// ---------------- driver ----------------------------------------------------
extern "C" void kernel_launch(void* const* d_in, const int* in_sizes, int n_in,
                              void* d_out, int out_size) {
    const float* x       = (const float*)d_in[0];
    const void*  ei      = d_in[1];
    const float* ea      = (const float*)d_in[2];
    const void*  bat     = d_in[3];
    const float* c1_w1   = (const float*)d_in[4];
    const float* c1_b1   = (const float*)d_in[5];
    const float* c1_w2   = (const float*)d_in[6];
    const float* c1_b2   = (const float*)d_in[7];
    const float* c1_root = (const float*)d_in[8];
    const float* c1_bias = (const float*)d_in[9];
    const float* c2_w1   = (const float*)d_in[10];
    const float* c2_b1   = (const float*)d_in[11];
    const float* c2_w2   = (const float*)d_in[12];
    const float* c2_b2   = (const float*)d_in[13];
    const float* c2_root = (const float*)d_in[14];
    const float* c2_bias = (const float*)d_in[15];
    const float* c3_w1   = (const float*)d_in[16];
    const float* c3_b1   = (const float*)d_in[17];
    const float* c3_w2   = (const float*)d_in[18];
    const float* c3_b2   = (const float*)d_in[19];
    const float* c3_root = (const float*)d_in[20];
    const float* c3_bias = (const float*)d_in[21];
    const float* fc1_w   = (const float*)d_in[22];
    const float* fc1_b   = (const float*)d_in[23];
    const float* fc2_w   = (const float*)d_in[24];
    const float* fc2_b   = (const float*)d_in[25];
    const float* fc3_w   = (const float*)d_in[26];
    const float* fc3_b   = (const float*)d_in[27];
    float* out = (float*)d_out;

    float *xa, *xb, *acc;
    cudaGetSymbolAddress((void**)&xa,  g_xa);
    cudaGetSymbolAddress((void**)&xb,  g_xb);
    cudaGetSymbolAddress((void**)&acc, g_acc);

    detect_kernel<<<1, 32>>>((const long long*)ei);
    convert_kernel<<<(NE + 255) / 256, 256>>>(ei, bat);

    // ---- layer 1: 13 -> 32
    edge_h_kernel<<<(NE * HID + 255) / 256, 256>>>(ea, c1_w1, c1_b1);
    root_kernel<13, 32><<<(NN * 32 + 255) / 256, 256>>>(x, c1_root, c1_bias, acc);
    msg_kernel<13, 32, 64><<<(NE + 63) / 64, 128>>>(x, c1_w2, c1_b2, acc);
    elu_kernel<<<(NN * 32 + 255) / 256, 256>>>(acc, xa, NN * 32);

    // ---- layer 2: 32 -> 64
    edge_h_kernel<<<(NE * HID + 255) / 256, 256>>>(ea, c2_w1, c2_b1);
    root_kernel<32, 64><<<(NN * 64 + 255) / 256, 256>>>(xa, c2_root, c2_bias, acc);
    msg_kernel<32, 64, 32><<<(NE + 31) / 32, 128>>>(xa, c2_w2, c2_b2, acc);
    elu_kernel<<<(NN * 64 + 255) / 256, 256>>>(acc, xb, NN * 64);

    // ---- layer 3: 64 -> 64
    edge_h_kernel<<<(NE * HID + 255) / 256, 256>>>(ea, c3_w1, c3_b1);
    root_kernel<64, 64><<<(NN * 64 + 255) / 256, 256>>>(xb, c3_root, c3_bias, acc);
    msg_kernel<64, 64, 32><<<(NE + 31) / 32, 128>>>(xb, c3_w2, c3_b2, acc);
    elu_kernel<<<(NN * 64 + 255) / 256, 256>>>(acc, xa, NN * 64);

    // ---- pooling + head
    pool_init_kernel<<<(NG * 64 + 255) / 256, 256>>>();
    pool_kernel<<<(NN * 64 + 255) / 256, 256>>>(xa);
    mlp_kernel<<<(NG + 127) / 128, 128>>>(fc1_w, fc1_b, fc2_w, fc2_b, fc3_w, fc3_b, out);
}